// round 17
// baseline (speedup 1.0000x reference)
#include <cuda_runtime.h>
#include <math.h>
#include <stdint.h>

#define Bq   8
#define Nq   1024
#define Hq   200
#define BNr  (Bq*Nq)
#define NCH  8
#define LQ   608

// dynamic smem: A [buf][pl][256*64B=16KB] -> 64KB ; B [buf][pl][4KB] -> 16KB
#define A_TOT   65536
#define SM_TOT  81920

// ---------------- scratch (no allocs allowed) ----------------
__device__ float g_outs  [BNr*Hq];
__device__ float g_output[BNr*Hq];
__device__ float g_bufA  [BNr*Hq];
__device__ float g_bufB  [BNr*Hq];
__device__ float g_bufC  [BNr*Hq];
__device__ float g_scores[Bq*Nq*Nq];
__device__ float g_scT   [Bq*Nq*Nq];
__device__ float g_qkv   [(long)BNr*LQ];
__device__ float g_wqkv  [3L*Hq*LQ];
__device__ float g_bqkv  [3*LQ];
__device__ float g_denom [BNr];
__device__ float g_rmax  [BNr];
__device__ float g_rsum  [BNr];
__device__ float g_cmax  [BNr];
__device__ float g_csum  [BNr];
__device__ float g_pmax  [NCH*BNr];
__device__ float g_psum  [NCH*BNr];

// ---------------- generic helpers ----------------
__device__ __forceinline__ float warp_red_sum(float v){
#pragma unroll
    for (int o=16;o;o>>=1) v += __shfl_xor_sync(0xffffffffu, v, o);
    return v;
}
__device__ __forceinline__ float warp_red_max(float v){
#pragma unroll
    for (int o=16;o;o>>=1) v = fmaxf(v, __shfl_xor_sync(0xffffffffu, v, o));
    return v;
}

// ---------------- tensor-core primitives (baseline PTX, no 'a' features) ----------------
__device__ __forceinline__ uint32_t s2u(const void* p){
    uint32_t a;
    asm("{ .reg .u64 t; cvta.to.shared.u64 t, %1; cvt.u32.u64 %0, t; }" : "=r"(a) : "l"(p));
    return a;
}
__device__ __forceinline__ uint32_t bfp(float x0, float x1){
    uint32_t r;
    asm("cvt.rn.bf16x2.f32 %0, %1, %2;" : "=r"(r) : "f"(x1), "f"(x0));
    return r;
}
__device__ __forceinline__ float blo(uint32_t h){ return __uint_as_float(h<<16); }
__device__ __forceinline__ float bhi(uint32_t h){ return __uint_as_float(h & 0xFFFF0000u); }
__device__ __forceinline__ void ldmx4(uint32_t* r, uint32_t addr){
    asm volatile("ldmatrix.sync.aligned.m8n8.x4.shared.b16 {%0,%1,%2,%3}, [%4];"
        : "=r"(r[0]),"=r"(r[1]),"=r"(r[2]),"=r"(r[3]) : "r"(addr));
}
__device__ __forceinline__ void ldmx4t(uint32_t* r, uint32_t addr){
    asm volatile("ldmatrix.sync.aligned.m8n8.x4.trans.shared.b16 {%0,%1,%2,%3}, [%4];"
        : "=r"(r[0]),"=r"(r[1]),"=r"(r[2]),"=r"(r[3]) : "r"(addr));
}
__device__ __forceinline__ void mma16(float* d, const uint32_t* a, const uint32_t* b){
    asm volatile("mma.sync.aligned.m16n8k16.row.col.f32.bf16.bf16.f32 "
        "{%0,%1,%2,%3}, {%4,%5,%6,%7}, {%8,%9}, {%0,%1,%2,%3};"
        : "+f"(d[0]),"+f"(d[1]),"+f"(d[2]),"+f"(d[3])
        : "r"(a[0]),"r"(a[1]),"r"(a[2]),"r"(a[3]), "r"(b[0]),"r"(b[1]));
}
__device__ __forceinline__ int swz4(int row){ return ((row>>1) ^ (row>>3)) & 3; }

// ---------------- mma.sync bf16x3 GEMM, 256x64 CTA tile, 64x32 warp tile ----------------
// C[b,i,j] = epi( sum_k A[b,i,k] * Bop[b,k,j] ), near-fp32 via
//   x = xh + xl (bf16 split), C += Ah*Bh + Ah*Bl + Al*Bh  (drop Al*Bl ~2^-16)
// BT: 0 = B stored [Kd, Nc'] row-major -> smem [k][n] + ldmatrix.trans
//     1 = B stored [Nc', Kd] row-major (native K-major, non-trans ldmatrix)
// EPI: 0 +bias(opt); 1 +bias+res; 2 gelu(+bias); 3 *scale+keymask(tm[gj]);
//      4 +pairmask; 5 relu(acc/st1[gi])+res; 6 acc*tm[gi]+res
// Requires M%256==0, Kd%4==0, lda/ldb%4==0, bases 16B-aligned; BT=0 also j0%8==0.
template<int BT,int EPI>
__global__ void __launch_bounds__(256,2)
mma_k(const float* __restrict__ A, const float* __restrict__ Bm, float* __restrict__ C,
      int M, int Nc, int Kd, int lda, int ldb, int ldc,
      long sA_, long sB_, long sC_,
      const float* __restrict__ bias, const float* __restrict__ res,
      const float* __restrict__ st1, const float* __restrict__ tm, float scale)
{
    extern __shared__ __align__(16) char smem[];
    const int b  = blockIdx.z;
    const int i0 = blockIdx.y*256, j0 = blockIdx.x*64;
    const int tid = threadIdx.x, lid = tid&31, wid = tid>>5;
    const int wm = wid&3, wn = wid>>2;
    const float* Ab = A + (long)b*sA_;
    const float* Bb = Bm + (long)b*sB_;
    const uint32_t smA = s2u(smem);

    float acc[4][4][4];
#pragma unroll
    for (int mt=0;mt<4;mt++)
#pragma unroll
        for (int nt=0;nt<4;nt++)
#pragma unroll
            for (int e=0;e<4;e++) acc[mt][nt][e]=0.f;

    float4 ra[4];      // A staging: 128 rows x 32 k per pass (2 passes)
    float4 rb1[2];     // B staging BT=1
    float4 rbt[2];     // B staging BT=0

    auto ldgA = [&](int k0, int h){
#pragma unroll
        for (int p=0;p<4;p++){
            int s = tid + p*256; int row = h*128 + (s>>3), kq = s&7;
            int gk = k0 + kq*4;
            ra[p] = (gk+3 < Kd) ? *(const float4*)&Ab[(long)(i0+row)*lda + gk]
                                : make_float4(0.f,0.f,0.f,0.f);
        }
    };
    auto stsA = [&](int buf, int h){
        uint32_t base = buf*32768u;
#pragma unroll
        for (int p=0;p<4;p++){
            int s = tid + p*256; int row = h*128 + (s>>3), kq = s&7;
            float4 v = ra[p];
            uint32_t h0 = bfp(v.x, v.y), h1 = bfp(v.z, v.w);
            uint32_t l0 = bfp(v.x - blo(h0), v.y - bhi(h0));
            uint32_t l1 = bfp(v.z - blo(h1), v.w - bhi(h1));
            uint32_t off = (uint32_t)(row*64 + ((((kq>>1) ^ swz4(row))&3)<<4) + (kq&1)*8);
            *(uint2*)(smem + base + off)          = make_uint2(h0, h1);
            *(uint2*)(smem + base + 16384 + off)  = make_uint2(l0, l1);
        }
    };
    auto ldgB = [&](int k0){
        if (BT==1){
#pragma unroll
            for (int p=0;p<2;p++){
                int s = tid + p*256; int row = s>>3, kq = s&7;
                int gj = j0 + row, gk = k0 + kq*4;
                rb1[p] = (gj < Nc && gk+3 < Kd) ? *(const float4*)&Bb[(long)gj*ldb + gk]
                                                : make_float4(0.f,0.f,0.f,0.f);
            }
        } else {
            int n0 = (tid&7)*8, kk = tid>>3;
            int gk = k0 + kk;
            bool ko = gk < Kd;
            int gn = j0 + n0;
            rbt[0] = (ko && gn+3 < Nc) ? *(const float4*)&Bb[(long)gk*ldb + gn]
                                       : make_float4(0.f,0.f,0.f,0.f);
            rbt[1] = (ko && gn+7 < Nc) ? *(const float4*)&Bb[(long)gk*ldb + gn + 4]
                                       : make_float4(0.f,0.f,0.f,0.f);
        }
    };
    auto stsB = [&](int buf){
        uint32_t boff0 = A_TOT + buf*8192u;
        if (BT==1){
#pragma unroll
            for (int p=0;p<2;p++){
                int s = tid + p*256; int row = s>>3, kq = s&7;
                float4 v = rb1[p];
                uint32_t h0 = bfp(v.x, v.y), h1 = bfp(v.z, v.w);
                uint32_t l0 = bfp(v.x - blo(h0), v.y - bhi(h0));
                uint32_t l1 = bfp(v.z - blo(h1), v.w - bhi(h1));
                uint32_t off = (uint32_t)(row*64 + ((((kq>>1) ^ swz4(row))&3)<<4) + (kq&1)*8);
                *(uint2*)(smem + boff0 + off)        = make_uint2(h0, h1);
                *(uint2*)(smem + boff0 + 4096 + off) = make_uint2(l0, l1);
            }
        } else {
            int g = tid&7, kk = tid>>3;
            float4 v0 = rbt[0], v1 = rbt[1];
            uint32_t h0 = bfp(v0.x, v0.y), h1 = bfp(v0.z, v0.w);
            uint32_t h2 = bfp(v1.x, v1.y), h3 = bfp(v1.z, v1.w);
            uint32_t l0 = bfp(v0.x - blo(h0), v0.y - bhi(h0));
            uint32_t l1 = bfp(v0.z - blo(h1), v0.w - bhi(h1));
            uint32_t l2 = bfp(v1.x - blo(h2), v1.y - bhi(h2));
            uint32_t l3 = bfp(v1.z - blo(h3), v1.w - bhi(h3));
            uint32_t off = (uint32_t)(kk*128 + (((g ^ (kk&7))&7)<<4));
            *(uint4*)(smem + boff0 + off)        = make_uint4(h0,h1,h2,h3);
            *(uint4*)(smem + boff0 + 4096 + off) = make_uint4(l0,l1,l2,l3);
        }
    };

    // per-lane fragment constants
    int arow[4], aswz[4];
#pragma unroll
    for (int mt=0;mt<4;mt++){
        arow[mt] = wm*64 + mt*16 + (lid&7) + ((lid>>3)&1)*8;
        aswz[mt] = swz4(arow[mt]);
    }
    const int akg = lid>>4;
    int brow[2], bswz[2];
#pragma unroll
    for (int jp=0;jp<2;jp++){
        brow[jp] = wn*32 + jp*16 + ((lid>>4)&1)*8 + (lid&7);
        bswz[jp] = swz4(brow[jp]);
    }
    const int bkg = (lid>>3)&1;
    const int tkrow = (lid&7) + ((lid>>3)&1)*8;   // BT=0 trans: k-row base within k16
    const int tng  = wn*4 + (lid>>4);             // BT=0 trans: n-group base (+jp*2)

    // compute one k16 step: B-first, then per-mt A fragments + 12 mmas
    auto compute = [&](int sel, int ks){
        uint32_t aH = smA + sel*32768u;
        uint32_t aL = aH + 16384u;
        uint32_t bH = smA + A_TOT + sel*8192u;
        uint32_t bL = bH + 4096u;
        uint32_t bfh[2][4], bfl[2][4];
        if (BT==1){
#pragma unroll
            for (int jp=0;jp<2;jp++){
                uint32_t boff = (uint32_t)(brow[jp]*64 + ((((2*ks+bkg) ^ bswz[jp])&3)<<4));
                ldmx4(bfh[jp], bH + boff);
                ldmx4(bfl[jp], bL + boff);
            }
        } else {
#pragma unroll
            for (int jp=0;jp<2;jp++){
                int krow = ks*16 + tkrow;
                int ngrp = tng + jp*2;
                uint32_t boff = (uint32_t)(krow*128 + (((ngrp ^ (krow&7))&7)<<4));
                ldmx4t(bfh[jp], bH + boff);
                ldmx4t(bfl[jp], bL + boff);
            }
        }
#pragma unroll
        for (int mt=0;mt<4;mt++){
            uint32_t aoff = (uint32_t)(arow[mt]*64 + ((((2*ks+akg) ^ aswz[mt])&3)<<4));
            uint32_t afh[4], afl[4];
            ldmx4(afh, aH + aoff);
            ldmx4(afl, aL + aoff);
#pragma unroll
            for (int nt=0;nt<4;nt++)
                mma16(acc[mt][nt], afh, &bfh[nt>>1][(nt&1)*2]);
#pragma unroll
            for (int nt=0;nt<4;nt++){
                mma16(acc[mt][nt], afh, &bfl[nt>>1][(nt&1)*2]);
                mma16(acc[mt][nt], afl, &bfh[nt>>1][(nt&1)*2]);
            }
        }
    };

    const int nch = (Kd + 31) >> 5;
    // prologue: stage chunk 0 into buf 0
    ldgA(0,0); stsA(0,0);
    ldgA(0,1); stsA(0,1);
    ldgB(0);   stsB(0);
    for (int c=0; c<nch; c++){
        __syncthreads();
        const int sel = c & 1, nsel = sel ^ 1;
        const bool more = (c+1 < nch);
        if (more){ ldgA((c+1)*32, 0); ldgB((c+1)*32); }
        compute(sel, 0);
        if (more){
            stsA(nsel, 0); stsB(nsel);
            ldgA((c+1)*32, 1);
        }
        compute(sel, 1);
        if (more){ stsA(nsel, 1); }
    }

    // ---- epilogue ----
#pragma unroll
    for (int mt=0;mt<4;mt++){
        int gmr = i0 + wm*64 + mt*16 + (lid>>2);
#pragma unroll
        for (int nt=0;nt<4;nt++){
            int gn0 = j0 + wn*32 + nt*8 + (lid&3)*2;
#pragma unroll
            for (int e=0;e<4;e++){
                int gi = gmr + (e>>1)*8;
                int gj = gn0 + (e&1);
                if (gj >= Nc) continue;
                float v = acc[mt][nt][e];
                long cidx = (long)b*sC_ + (long)gi*ldc + gj;
                if (EPI==0){ if (bias) v += bias[gj]; }
                else if (EPI==1){ v += bias[gj]; v += res[cidx]; }
                else if (EPI==2){ v += bias[gj]; v = 0.5f*v*(1.f+erff(v*0.70710678f)); }
                else if (EPI==3){ v = v*scale + (tm[b*Nq+gj]-1.f)*10000.f; }
                else if (EPI==4){ v = v + (tm[b*Nq+gi]*tm[b*Nq+gj]-1.f)*10000.f; }
                else if (EPI==5){ v = fmaxf(v/st1[b*M+gi], 0.f) + res[cidx]; }
                else if (EPI==6){ v = v*tm[b*Nq+gi] + res[cidx]; }
                C[cidx] = v;
            }
        }
    }
}

// ---------------- softmax / stats ----------------
template<bool WRITE>
__global__ void __launch_bounds__(256)
softmax_row_k(float* __restrict__ S, float* __restrict__ rmax, float* __restrict__ rsum){
    long row = blockIdx.x;
    float* p = S + row*(long)Nq;
    int t = threadIdx.x;
    float v[4];
    float mx = -1e30f;
#pragma unroll
    for (int l=0;l<4;l++){ v[l]=p[t+l*256]; mx=fmaxf(mx,v[l]); }
    __shared__ float sm[8];
    mx = warp_red_max(mx);
    if ((t&31)==0) sm[t>>5]=mx;
    __syncthreads();
    float m2 = sm[0];
#pragma unroll
    for (int w=1;w<8;w++) m2 = fmaxf(m2, sm[w]);
    float s = 0.f;
#pragma unroll
    for (int l=0;l<4;l++){ v[l]=__expf(v[l]-m2); s+=v[l]; }
    __syncthreads();
    s = warp_red_sum(s);
    if ((t&31)==0) sm[t>>5]=s;
    __syncthreads();
    float st = 0.f;
#pragma unroll
    for (int w=0;w<8;w++) st += sm[w];
    if (WRITE){
        float inv = 1.f/st;
#pragma unroll
        for (int l=0;l<4;l++) p[t+l*256] = v[l]*inv;
    } else if (t==0){ rmax[row]=m2; rsum[row]=st; }
}

__global__ void __launch_bounds__(256)
colstats_part(const float* __restrict__ L, float* __restrict__ pmax, float* __restrict__ psum){
    int g  = blockIdx.x*256 + threadIdx.x;
    int ch = blockIdx.y;
    int b = g >> 10, m = g & 1023;
    const float* p = L + (long)b*Nq*Nq + m + (long)ch*(Nq/NCH)*Nq;
    float mx=-1e30f, s=0.f;
#pragma unroll 4
    for (int n=0;n<Nq/NCH;n++){
        float x = p[(long)n*Nq];
        if (x>mx){ s = s*__expf(mx-x) + 1.f; mx = x; }
        else       s += __expf(x-mx);
    }
    pmax[ch*BNr+g]=mx; psum[ch*BNr+g]=s;
}
__global__ void __launch_bounds__(256)
colstats_comb(const float* __restrict__ pmax, const float* __restrict__ psum,
              float* __restrict__ cmax, float* __restrict__ csum){
    int g = blockIdx.x*256 + threadIdx.x;
    float mx=-1e30f, s=0.f;
#pragma unroll
    for (int ch=0; ch<NCH; ch++){
        float m2=pmax[ch*BNr+g], s2=psum[ch*BNr+g];
        if (m2>mx){ s = s*__expf(mx-m2) + s2; mx = m2; }
        else        s += s2*__expf(m2-mx);
    }
    cmax[g]=mx; csum[g]=s;
}

// ---------------- dual normalize: P_row in place, P_col^T transposed ----------------
__global__ void __launch_bounds__(256)
normalize_dual(float* __restrict__ L, float* __restrict__ LT,
               const float* __restrict__ rmax, const float* __restrict__ rsum,
               const float* __restrict__ cmax, const float* __restrict__ csum){
    __shared__ float sm[32][33];
    int b = blockIdx.z;
    int i0 = blockIdx.y*32, j0 = blockIdx.x*32;
    int tx = threadIdx.x & 31, ty = threadIdx.x >> 5;
    float* Lb  = L  + (long)b*Nq*Nq;
    float* LTb = LT + (long)b*Nq*Nq;
    int gb = b*Nq;
#pragma unroll
    for (int p=0;p<4;p++){
        int ti = ty + p*8;
        int gi = i0+ti, gj = j0+tx;
        float l = Lb[(long)gi*Nq + gj];
        Lb[(long)gi*Nq + gj] = __expf(l - rmax[gb+gi]) / rsum[gb+gi];
        sm[ti][tx] = __expf(l - cmax[gb+gj]) / csum[gb+gj];
    }
    __syncthreads();
#pragma unroll
    for (int p=0;p<4;p++){
        int tj = ty + p*8;
        LTb[(long)(j0+tj)*Nq + i0 + tx] = sm[tx][tj];
    }
}

// ---------------- layernorm (1 warp / row, H=200) ----------------
__global__ void __launch_bounds__(32)
ln_k(const float* __restrict__ X, const float* __restrict__ g,
     const float* __restrict__ bt, float* __restrict__ Y){
    long row = blockIdx.x;
    const float* x = X + row*Hq;
    float* y = Y + row*Hq;
    int t = threadIdx.x;
    float v[7]; float s=0.f;
#pragma unroll
    for (int l=0;l<7;l++){ int c=t+l*32; v[l]=(c<Hq)?x[c]:0.f; s+=v[l]; }
    s = warp_red_sum(s);
    float mu = s*(1.f/Hq);
    float var = 0.f;
#pragma unroll
    for (int l=0;l<7;l++){ int c=t+l*32; if (c<Hq){ float d=v[l]-mu; var+=d*d; } }
    var = warp_red_sum(var)*(1.f/Hq);
    float r = rsqrtf(var + 1e-20f);
#pragma unroll
    for (int l=0;l<7;l++){ int c=t+l*32; if (c<Hq) y[c] = (v[l]-mu)*r*g[c]+bt[c]; }
}

// ---------------- adj + denom ----------------
__global__ void __launch_bounds__(256)
adj_k(const float* __restrict__ a1, const float* __restrict__ a2,
      float* __restrict__ adjo, float* __restrict__ den){
    long row = blockIdx.x;
    long base = row*(long)Nq;
    int t = threadIdx.x;
    float s = 0.f;
#pragma unroll
    for (int l=0;l<4;l++){
        int m = t+l*256;
        float v = fminf(a1[base+m]+a2[base+m], 1.f);
        adjo[base+m]=v; s+=v;
    }
    __shared__ float sm[8];
    s = warp_red_sum(s);
    if ((t&31)==0) sm[t>>5]=s;
    __syncthreads();
    if (t==0){
        float tot=0.f;
#pragma unroll
        for (int w=0;w<8;w++) tot+=sm[w];
        den[row]=tot+1e-7f;
    }
}

__global__ void init_k(const float* __restrict__ text, float* __restrict__ o1, float* __restrict__ o2){
    for (long i = blockIdx.x*256L + threadIdx.x; i < (long)BNr*Hq; i += (long)gridDim.x*256)
    { float v=text[i]; o1[i]=v; o2[i]=v; }
}

// ---------------- qkv weight/bias pack: [3][200][608] and [3][608] ----------------
__global__ void wpack_k(const float* __restrict__ qw, const float* __restrict__ kw,
                        const float* __restrict__ vw, const float* __restrict__ qb,
                        const float* __restrict__ kb, const float* __restrict__ vb,
                        float* __restrict__ wq, float* __restrict__ bq){
    const long tot = 3L*Hq*LQ;
    for (long x = blockIdx.x*256L + threadIdx.x; x < tot; x += (long)gridDim.x*256){
        int i = (int)(x / (Hq*LQ)); int rem = (int)(x % (Hq*LQ));
        int k = rem / LQ, n = rem % LQ;
        float v = 0.f;
        if      (n < 200) v = qw[((long)i*Hq + k)*Hq + n];
        else if (n < 400) v = kw[((long)i*Hq + k)*Hq + (n-200)];
        else if (n < 600) v = vw[((long)i*Hq + k)*Hq + (n-400)];
        wq[x] = v;
    }
    for (long x = blockIdx.x*256L + threadIdx.x; x < 3*LQ; x += (long)gridDim.x*256){
        int i = (int)(x / LQ), n = (int)(x % LQ);
        float v = 0.f;
        if      (n < 200) v = qb[i*Hq + n];
        else if (n < 400) v = kb[i*Hq + n-200];
        else if (n < 600) v = vb[i*Hq + n-400];
        bq[x] = v;
    }
}

// ---------------- host-side GEMM launcher ----------------
template<int BT,int EPI>
static void MG(const float*A,const float*Bm,float*C,int M,int Nc,int Kd,
               int lda,int ldb,int ldc,long sa,long sb,long sc_,int batch,
               const float*bias,const float*res,const float*st1,const float*tmv,float scale){
    static bool cfg = false;
    if (!cfg){
        cudaFuncSetAttribute(mma_k<BT,EPI>, cudaFuncAttributeMaxDynamicSharedMemorySize, SM_TOT);
        cfg = true;
    }
    dim3 grid((Nc+63)/64, M/256, batch);
    mma_k<BT,EPI><<<grid,256,SM_TOT>>>(A,Bm,C,M,Nc,Kd,lda,ldb,ldc,sa,sb,sc_,bias,res,st1,tmv,scale);
}

extern "C" void kernel_launch(void* const* d_in, const int* in_sizes, int n_in,
                              void* d_out, int out_size)
{
    const float* text  = (const float*)d_in[0];
    const float* adj1  = (const float*)d_in[1];
    const float* adj2  = (const float*)d_in[2];
    const float* tmask = (const float*)d_in[5];
    const float* gcn_w = (const float*)d_in[6];
    const float* mut_w = (const float*)d_in[7];
    const float* qw=(const float*)d_in[8],  *qb=(const float*)d_in[9];
    const float* kw=(const float*)d_in[10], *kb=(const float*)d_in[11];
    const float* vw=(const float*)d_in[12], *vb=(const float*)d_in[13];
    const float* aw=(const float*)d_in[14], *ab=(const float*)d_in[15];
    const float* g1=(const float*)d_in[16], *b1=(const float*)d_in[17];
    const float* iw=(const float*)d_in[18], *ib=(const float*)d_in[19];
    const float* ow=(const float*)d_in[20], *ob=(const float*)d_in[21];
    const float* g2=(const float*)d_in[22], *b2=(const float*)d_in[23];

    float* out  = (float*)d_out;
    float* adjo = out + (long)BNr*Hq;     // adj output region

    void* p;
    cudaGetSymbolAddress(&p, g_outs);   float* outs=(float*)p;
    cudaGetSymbolAddress(&p, g_output); float* outp=(float*)p;
    cudaGetSymbolAddress(&p, g_bufA);   float* bA=(float*)p;
    cudaGetSymbolAddress(&p, g_bufB);   float* bB=(float*)p;
    cudaGetSymbolAddress(&p, g_bufC);   float* bC=(float*)p;
    cudaGetSymbolAddress(&p, g_scores); float* sc=(float*)p;
    cudaGetSymbolAddress(&p, g_scT);    float* scT=(float*)p;
    cudaGetSymbolAddress(&p, g_qkv);    float* qkvb=(float*)p;
    cudaGetSymbolAddress(&p, g_wqkv);   float* wq=(float*)p;
    cudaGetSymbolAddress(&p, g_bqkv);   float* bq=(float*)p;
    cudaGetSymbolAddress(&p, g_denom);  float* den=(float*)p;
    cudaGetSymbolAddress(&p, g_rmax);   float* rmax=(float*)p;
    cudaGetSymbolAddress(&p, g_rsum);   float* rsum=(float*)p;
    cudaGetSymbolAddress(&p, g_cmax);   float* cmax=(float*)p;
    cudaGetSymbolAddress(&p, g_csum);   float* csum=(float*)p;
    cudaGetSymbolAddress(&p, g_pmax);   float* pmax=(float*)p;
    cudaGetSymbolAddress(&p, g_psum);   float* psum=(float*)p;

    const long sNH = (long)Nq*Hq;
    const long sNN = (long)Nq*Nq;
    const long sNQ = (long)Nq*LQ;
    const float rscale = 1.0f/sqrtf((float)Hq);

    init_k<<<640,256>>>(text, outs, outp);
    adj_k<<<BNr,256>>>(adj1, adj2, adjo, den);
    wpack_k<<<640,256>>>(qw,kw,vw,qb,kb,vb, wq,bq);

    for (int i=0;i<3;i++){
        const float *wqi=wq + (long)i*Hq*LQ, *bqi=bq + i*LQ;
        const float *awi=aw+i*Hq*Hq, *abi=ab+i*Hq;
        const float *iwi=iw+i*Hq*Hq, *ibi=ib+i*Hq;
        const float *owi=ow+i*Hq*Hq, *obi=ob+i*Hq;
        const float *g1i=g1+i*Hq, *b1i=b1+i*Hq, *g2i=g2+i*Hq, *b2i=b2+i*Hq;

        // ---- BERT layer ----
        MG<0,0>(outs,wqi,qkvb, BNr,600,Hq, Hq,LQ,LQ, 0,0,0, 1, bqi,0,0,0,0.f);          // q|k|v fused
        MG<1,3>(qkvb, qkvb+200, sc, Nq,Nq,Hq, LQ,LQ,Nq, sNQ,sNQ,sNN, Bq, 0,0,0, tmask, rscale); // scores
        softmax_row_k<true><<<BNr,256>>>(sc, 0, 0);
        MG<0,0>(sc, qkvb+400, bA, Nq,Hq,Nq, Nq,LQ,Hq, sNN,sNQ,sNH, Bq, 0,0,0,0,0.f);    // ctx
        MG<0,1>(bA,awi,bB, BNr,Hq,Hq, Hq,Hq,Hq, 0,0,0, 1, abi, outs, 0,0,0.f);          // pre-LN1
        ln_k<<<BNr,32>>>(bB, g1i, b1i, bC);                                              // attn
        MG<0,2>(bC,iwi,bA, BNr,Hq,Hq, Hq,Hq,Hq, 0,0,0, 1, ibi,0,0,0,0.f);               // inter (gelu)
        MG<0,1>(bA,owi,bB, BNr,Hq,Hq, Hq,Hq,Hq, 0,0,0, 1, obi, bC, 0,0,0.f);            // pre-LN2
        ln_k<<<BNr,32>>>(bB, g2i, b2i, outs);                                            // outs updated

        // ---- GCN propagation ----
        MG<0,0>(outp,gcn_w,bA, BNr,Hq,Hq, Hq,Hq,Hq, 0,0,0, 1, 0,0,0,0,0.f);             // teout
        MG<0,5>(adjo,bA,bB, Nq,Hq,Nq, Nq,Hq,Hq, sNN,sNH,sNH, Bq, 0, outp, den, 0, 0.f);
        { float* t_=outp; outp=bB; bB=t_; }

        // ---- self-alignment ----
        MG<0,0>(outs,mut_w,bA, BNr,Hq,Hq, Hq,Hq,Hq, 0,0,0, 1, 0,0,0,0,0.f);             // mo
        MG<1,4>(bA,outp,sc, Nq,Nq,Hq, Hq,Hq,Nq, sNH,sNH,sNN, Bq, 0,0,0, tmask, 0.f);    // logit
        softmax_row_k<false><<<BNr,256>>>(sc, rmax, rsum);
        colstats_part<<<dim3(BNr/256,NCH),256>>>(sc, pmax, psum);
        colstats_comb<<<BNr/256,256>>>(pmax, psum, cmax, csum);
        normalize_dual<<<dim3(Nq/32,Nq/32,Bq),256>>>(sc, scT, rmax, rsum, cmax, csum);
        MG<0,6>(sc,  outp, bC, Nq,Hq,Nq, Nq,Hq,Hq, sNN,sNH,sNH, Bq, 0, outs, 0, tmask, 0.f); // new_outs
        MG<0,6>(scT, outs, bB, Nq,Hq,Nq, Nq,Hq,Hq, sNN,sNH,sNH, Bq, 0, outp, 0, tmask, 0.f); // new_output
        { float* t_=outs; outs=bC; bC=t_; }
        { float* t_=outp; outp=bB; bB=t_; }
    }

    cudaMemcpyAsync(out, outs, (size_t)BNr*Hq*sizeof(float), cudaMemcpyDeviceToDevice);
}